// round 5
// baseline (speedup 1.0000x reference)
#include <cuda_runtime.h>
#include <cstdint>

// rosa_emb_layer: B=8, T=2048, V=50257, C=768
// inputs: d_in[0] = idx (B,T) int32, d_in[1] = emb (V,C) float32
// output: (B,T,C) float32
//
// R4: keep R3's fused hash-chain match (expected ~42 matching pairs per
// batch; (L<<11)|j integer max reproduces the L + j*1e-5 argmax exactly).
// NEW: zero rows (99.98% of output bytes) are written with TMA bulk stores
// (cp.async.bulk.global.shared::cta) from a static 3KB zero buffer in smem,
// bypassing the STG->L2 write path that every previous variant saturated at
// ~1/3 LTS cap. Match rows (rare) still use plain LDG/STG copies.

#define TT 2048
#define BB 8
#define CC 768
#define HSZ 4096
#define ROWB (CC * 4)   // bytes per output row = 3072

__global__ __launch_bounds__(256)
void rosa_fused_kernel(const int* __restrict__ idx,
                       const float* __restrict__ emb,
                       float* __restrict__ out) {
    __shared__ int   xs[TT];
    __shared__ int   head[HSZ];
    __shared__ int   nxt[TT];
    __shared__ int   pred[32];
    __shared__ __align__(128) float zbuf[CC];   // 3KB of zeros (TMA source)

    const int b     = blockIdx.x >> 6;          // 64 CTAs per batch
    const int rbase = (blockIdx.x & 63) << 5;   // 32 rows per CTA
    const int tid   = threadIdx.x;

    // Prologue: token row (8KB), hash heads, zero buffer.
    const int4* g = (const int4*)(idx + (size_t)b * TT);
    ((int4*)xs)[tid]       = g[tid];
    ((int4*)xs)[tid + 256] = g[tid + 256];
    const int4 neg = make_int4(-1, -1, -1, -1);
    #pragma unroll
    for (int k = 0; k < HSZ / 4 / 256; k++) ((int4*)head)[tid + 256 * k] = neg;
    if (tid < CC / 4) ((float4*)zbuf)[tid] = make_float4(0.f, 0.f, 0.f, 0.f);
    // Make generic smem writes (zbuf) visible to the async (TMA) proxy.
    asm volatile("fence.proxy.async.shared::cta;" ::: "memory");
    __syncthreads();

    // Build per-value linked lists (chain order irrelevant: we take a max).
    #pragma unroll
    for (int k = 0; k < TT / 256; k++) {
        const int i = tid + 256 * k;
        nxt[i] = atomicExch(&head[xs[i] & (HSZ - 1)], i);
    }
    __syncthreads();

    // 32 threads: walk chain for row rbase+tid, backward-extend on matches.
    if (tid < 32) {
        const int i  = rbase + tid;
        const int xi = xs[i];
        int best = 0;                            // (L<<11)|j ; 0 == no match
        for (int j = head[xi & (HSZ - 1)]; j >= 0; j = nxt[j]) {
            if (j < i && xs[j] == xi) {
                int L = 1, t = 1;
                while (t <= j && xs[i - t] == xs[j - t]) { ++L; ++t; }
                const int p = (L << 11) | j;
                if (p > best) best = p;
            }
        }
        int tok = -1;
        if (best >= (1 << 11)) {
            int pi = (best & 2047) + 1;
            if (pi > TT - 1) pi = TT - 1;
            tok = xs[pi];
        }
        pred[tid] = tok;
    }
    __syncthreads();

    float* const obase = out + ((size_t)b * TT + rbase) * CC;

    // Zero rows: thread r (r<32) TMA-bulk-stores row r from the shared zero
    // buffer. One instruction per 3KB row, async-proxy path (no STG).
    if (tid < 32 && pred[tid] < 0) {
        uint32_t zaddr;
        asm volatile("{ .reg .u64 t; cvta.to.shared.u64 t, %1; cvt.u32.u64 %0, t; }"
                     : "=r"(zaddr) : "l"(zbuf));
        asm volatile("cp.async.bulk.global.shared::cta.bulk_group [%0], [%1], %2;"
                     :: "l"(obase + (size_t)tid * CC), "r"(zaddr), "n"(ROWB)
                     : "memory");
        asm volatile("cp.async.bulk.commit_group;" ::: "memory");
    }

    // Match rows (rare): warp w copies emb rows for rows 4w..4w+3 via LDG/STG.
    const int w = tid >> 5, lane = tid & 31;
    #pragma unroll
    for (int r = 0; r < 4; r++) {
        const int row = 4 * w + r;
        const int tok = pred[row];
        if (tok >= 0) {
            const float4* e = (const float4*)(emb + (size_t)tok * CC);
            float4* orow = (float4*)(obase + (size_t)row * CC);
            #pragma unroll
            for (int k = 0; k < CC / 4 / 32; k++)
                orow[lane + 32 * k] = e[lane + 32 * k];
        }
    }

    // Drain this thread's bulk-store group before smem is torn down.
    if (tid < 32)
        asm volatile("cp.async.bulk.wait_group 0;" ::: "memory");
}

extern "C" void kernel_launch(void* const* d_in, const int* in_sizes, int n_in,
                              void* d_out, int out_size) {
    const int*   idx = (const int*)d_in[0];
    const float* emb = (const float*)d_in[1];
    float*       out = (float*)d_out;

    rosa_fused_kernel<<<BB * 64, 256>>>(idx, emb, out);
}

// round 6
// speedup vs baseline: 1.1975x; 1.1975x over previous
#include <cuda_runtime.h>

// rosa_emb_layer: B=8, T=2048, V=50257, C=768
// inputs: d_in[0] = idx (B,T) int32, d_in[1] = emb (V,C) float32
// output: (B,T,C) float32
//
// R5 = R1 (best, 12.8us) + 256-bit stores (st.global.v8.f32, sm_100+).
// Evidence so far: output write (50MB, L2-resident) is the wall at
// ~4.2 TB/s, path-independent (STG == TMA). R1's shape (2048 CTAs x 8 warps,
// one warp per output row, occ 75%) is the fastest extractor; v8 stores
// halve store instructions + L1TEX store wavefronts per byte.

#define TT 2048
#define BB 8
#define CC 768
#define WPB 8  // warps per CTA

__device__ __forceinline__ void stg_v8(float* p,
                                       float a, float b, float c, float d,
                                       float e, float f, float g, float h) {
    asm volatile("st.global.v8.f32 [%0], {%1,%2,%3,%4,%5,%6,%7,%8};"
                 :: "l"(p), "f"(a), "f"(b), "f"(c), "f"(d),
                    "f"(e), "f"(f), "f"(g), "f"(h) : "memory");
}

__device__ __forceinline__ void ldg_v8(const float* p, float* r) {
    asm volatile("ld.global.nc.v8.f32 {%0,%1,%2,%3,%4,%5,%6,%7}, [%8];"
                 : "=f"(r[0]), "=f"(r[1]), "=f"(r[2]), "=f"(r[3]),
                   "=f"(r[4]), "=f"(r[5]), "=f"(r[6]), "=f"(r[7])
                 : "l"(p));
}

__global__ __launch_bounds__(256, 8)
void rosa_emb_kernel(const int* __restrict__ idx,
                     const float* __restrict__ emb,
                     float* __restrict__ out) {
    __shared__ int xs[TT];

    const int cta_per_b = TT / WPB;               // 256
    const int b      = blockIdx.x / cta_per_b;
    const int i_base = (blockIdx.x % cta_per_b) * WPB;
    const int tid  = threadIdx.x;
    const int w    = tid >> 5;
    const int lane = tid & 31;

    // Cooperatively load this batch's token row (8 KB) into shared memory.
    const int4* g  = (const int4*)(idx + (size_t)b * TT);
    int4*       s4 = (int4*)xs;
    #pragma unroll
    for (int k = tid; k < TT / 4; k += 256) s4[k] = g[k];
    __syncthreads();

    const int i  = i_base + w;
    const int xi = xs[i];

    // best = (L << 11) | j  (L in [1,2048], j in [0,2047]); 0 == no match.
    // Integer max reproduces argmax(L + j*1e-5) with larger-j tie-break.
    int best = 0;

    // Lanes cover j in [0, i) with int4 chunks: lane -> j0 = 4*lane + 128*k.
    for (int j0 = lane * 4; j0 < i; j0 += 128) {
        const int4 v = s4[j0 >> 2];
        const bool m0 = (v.x == xi);                    // j0 < i guaranteed
        const bool m1 = (v.y == xi) & (j0 + 1 < i);
        const bool m2 = (v.z == xi) & (j0 + 2 < i);
        const bool m3 = (v.w == xi) & (j0 + 3 < i);
        if (m0 | m1 | m2 | m3) {                        // rare (~1/12500 per elt)
            #pragma unroll
            for (int c = 0; c < 4; c++) {
                const bool m = (c == 0) ? m0 : (c == 1) ? m1 : (c == 2) ? m2 : m3;
                if (m) {
                    const int j = j0 + c;
                    int L = 1, t = 1;
                    while (t <= j && xs[i - t] == xs[j - t]) { ++L; ++t; }
                    const int packed = (L << 11) | j;
                    if (packed > best) best = packed;
                }
            }
        }
    }

    // Warp max-reduce the packed (L, j) score.
    #pragma unroll
    for (int o = 16; o; o >>= 1)
        best = max(best, __shfl_xor_sync(0xffffffffu, best, o));

    // Fused epilogue: this warp writes its (b,i) row of 768 floats with
    // three 256-bit stores per lane (row = 96 octets; lane, lane+32, lane+64).
    float* orow = out + ((size_t)b * TT + i) * CC;
    if (best < (1 << 11)) {
        #pragma unroll
        for (int k = 0; k < 3; k++)
            stg_v8(orow + (lane + 32 * k) * 8,
                   0.f, 0.f, 0.f, 0.f, 0.f, 0.f, 0.f, 0.f);
    } else {
        const int bj   = best & 2047;
        int pidx = bj + 1; if (pidx > TT - 1) pidx = TT - 1;
        const int tok  = xs[pidx];
        const float* erow = emb + (size_t)tok * CC;
        float r[24];
        #pragma unroll
        for (int k = 0; k < 3; k++)
            ldg_v8(erow + (lane + 32 * k) * 8, r + 8 * k);
        #pragma unroll
        for (int k = 0; k < 3; k++)
            stg_v8(orow + (lane + 32 * k) * 8,
                   r[8*k], r[8*k+1], r[8*k+2], r[8*k+3],
                   r[8*k+4], r[8*k+5], r[8*k+6], r[8*k+7]);
    }
}

extern "C" void kernel_launch(void* const* d_in, const int* in_sizes, int n_in,
                              void* d_out, int out_size) {
    const int*   idx = (const int*)d_in[0];
    const float* emb = (const float*)d_in[1];
    float*       out = (float*)d_out;

    rosa_emb_kernel<<<BB * (TT / WPB), 256>>>(idx, emb, out);
}

// round 7
// speedup vs baseline: 1.2005x; 1.0025x over previous
#include <cuda_runtime.h>

// rosa_emb_layer: B=8, T=2048, V=50257, C=768
// inputs: d_in[0] = idx (B,T) int32, d_in[1] = emb (V,C) float32
// output: (B,T,C) float32
//
// R6 = R1 shape + OPTIMISTIC ZERO STORES. Evidence: store path is drain-
// limited (~4.25 TB/s dirty-write L2 acceptance; v8==v4, TMA==STG). 99.98%
// of rows are zero, so every warp fires its 3x st.global.v8 zero stores at
// cycle 0 (before smem fill / compare loop), letting the drain overlap all
// compute. Matched rows (~42 total) are fixed up at the end by overwriting
// with emb data from the same lanes (per-thread same-address order).

#define TT 2048
#define BB 8
#define CC 768
#define WPB 8  // warps per CTA

__device__ __forceinline__ void stg_v8(float* p,
                                       float a, float b, float c, float d,
                                       float e, float f, float g, float h) {
    asm volatile("st.global.v8.f32 [%0], {%1,%2,%3,%4,%5,%6,%7,%8};"
                 :: "l"(p), "f"(a), "f"(b), "f"(c), "f"(d),
                    "f"(e), "f"(f), "f"(g), "f"(h) : "memory");
}

__device__ __forceinline__ void ldg_v8(const float* p, float* r) {
    asm volatile("ld.global.nc.v8.f32 {%0,%1,%2,%3,%4,%5,%6,%7}, [%8];"
                 : "=f"(r[0]), "=f"(r[1]), "=f"(r[2]), "=f"(r[3]),
                   "=f"(r[4]), "=f"(r[5]), "=f"(r[6]), "=f"(r[7])
                 : "l"(p));
}

__global__ __launch_bounds__(256, 8)
void rosa_emb_kernel(const int* __restrict__ idx,
                     const float* __restrict__ emb,
                     float* __restrict__ out) {
    __shared__ int xs[TT];

    const int cta_per_b = TT / WPB;               // 256
    const int b      = blockIdx.x / cta_per_b;
    const int i_base = (blockIdx.x % cta_per_b) * WPB;
    const int tid  = threadIdx.x;
    const int w    = tid >> 5;
    const int lane = tid & 31;
    const int i    = i_base + w;

    // ---- Phase 0: fire this warp's zero row IMMEDIATELY (no deps). ----
    float* orow = out + ((size_t)b * TT + i) * CC;
    #pragma unroll
    for (int k = 0; k < 3; k++)
        stg_v8(orow + (lane + 32 * k) * 8,
               0.f, 0.f, 0.f, 0.f, 0.f, 0.f, 0.f, 0.f);

    // ---- Phase 1: load this batch's token row (8 KB) into shared. ----
    const int4* g  = (const int4*)(idx + (size_t)b * TT);
    int4*       s4 = (int4*)xs;
    #pragma unroll
    for (int k = tid; k < TT / 4; k += 256) s4[k] = g[k];
    __syncthreads();

    const int xi = xs[i];

    // best = (L << 11) | j  (L in [1,2048], j in [0,2047]); 0 == no match.
    // Integer max reproduces argmax(L + j*1e-5) with larger-j tie-break.
    int best = 0;

    // Lanes cover j in [0, i) with int4 chunks: lane -> j0 = 4*lane + 128*k.
    for (int j0 = lane * 4; j0 < i; j0 += 128) {
        const int4 v = s4[j0 >> 2];
        const bool m0 = (v.x == xi);                    // j0 < i guaranteed
        const bool m1 = (v.y == xi) & (j0 + 1 < i);
        const bool m2 = (v.z == xi) & (j0 + 2 < i);
        const bool m3 = (v.w == xi) & (j0 + 3 < i);
        if (m0 | m1 | m2 | m3) {                        // rare (~1/12500 per elt)
            #pragma unroll
            for (int c = 0; c < 4; c++) {
                const bool m = (c == 0) ? m0 : (c == 1) ? m1 : (c == 2) ? m2 : m3;
                if (m) {
                    const int j = j0 + c;
                    int L = 1, t = 1;
                    while (t <= j && xs[i - t] == xs[j - t]) { ++L; ++t; }
                    const int packed = (L << 11) | j;
                    if (packed > best) best = packed;
                }
            }
        }
    }

    // Warp max-reduce the packed (L, j) score.
    #pragma unroll
    for (int o = 16; o; o >>= 1)
        best = max(best, __shfl_xor_sync(0xffffffffu, best, o));

    // ---- Phase 2 (rare): overwrite matched row with emb data. Same lanes
    // rewrite the same addresses they zeroed -> per-thread coherence orders it.
    if (best >= (1 << 11)) {
        const int bj = best & 2047;
        int pidx = bj + 1; if (pidx > TT - 1) pidx = TT - 1;
        const int tok = xs[pidx];
        const float* erow = emb + (size_t)tok * CC;
        float r[24];
        #pragma unroll
        for (int k = 0; k < 3; k++)
            ldg_v8(erow + (lane + 32 * k) * 8, r + 8 * k);
        #pragma unroll
        for (int k = 0; k < 3; k++)
            stg_v8(orow + (lane + 32 * k) * 8,
                   r[8*k], r[8*k+1], r[8*k+2], r[8*k+3],
                   r[8*k+4], r[8*k+5], r[8*k+6], r[8*k+7]);
    }
}

extern "C" void kernel_launch(void* const* d_in, const int* in_sizes, int n_in,
                              void* d_out, int out_size) {
    const int*   idx = (const int*)d_in[0];
    const float* emb = (const float*)d_in[1];
    float*       out = (float*)d_out;

    rosa_emb_kernel<<<BB * (TT / WPB), 256>>>(idx, emb, out);
}